// round 8
// baseline (speedup 1.0000x reference)
#include <cuda_runtime.h>

// ---------------------------------------------------------------------------
// LSTM_10522669875315 — fp32 SIMT baseline with algorithmic restructuring:
//  * token->xproj lookup table (VOCAB=10, EMBED=10)
//  * gate-interleaved recurrent weight matrix (row 4u+gate) so the c/h
//    update is local to the GEMM tile owner
//  * 256 step-kernels in the captured graph, double-buffered h
//  * packed f32x2 FMA (FFMA2) inner loop: 128 MACs/cyc/SM
// ---------------------------------------------------------------------------

#define BATCH 256
#define SEQT  256
#define HID   1024
#define G4H   4096
#define EMB   10
#define NVOC  10
#define NCLS  10

// Device-global scratch (allocation-free rule: __device__ arrays)
__device__ float g_Wr[G4H * HID];          // 16 MB: interleaved recurrent weights
__device__ float g_xt[NVOC * G4H];         // 160 KB: per-token projected gate bias table
__device__ float g_h[2][BATCH * HID];      // double-buffered hidden state
__device__ float g_c[BATCH * HID];         // cell state (exclusive ownership per elem)
__device__ int   g_xflag;                  // 1 if tokens are int64, 0 if int32

// ---------------------------------------------------------------------------
// f32x2 packed helpers (FFMA2 only reachable via PTX fma.rn.f32x2)
// ---------------------------------------------------------------------------
typedef unsigned long long u64;

__device__ __forceinline__ u64 pk2(float x, float y) {
    u64 r;
    asm("mov.b64 %0, {%1, %2};" : "=l"(r) : "f"(x), "f"(y));
    return r;
}
__device__ __forceinline__ void upk2(u64 v, float& x, float& y) {
    asm("mov.b64 {%0, %1}, %2;" : "=f"(x), "=f"(y) : "l"(v));
}
__device__ __forceinline__ u64 ffma2(u64 a, u64 b, u64 c) {
    u64 d;
    asm("fma.rn.f32x2 %0, %1, %2, %3;" : "=l"(d) : "l"(a), "l"(b), "l"(c));
    return d;
}

// ---------------------------------------------------------------------------
// Detect token dtype: int64 little-endian 0..9 => every odd 32-bit word is 0.
// (For actual int32 tokens, 32 consecutive odd slots all being 0 has
//  probability 1e-32 — effectively impossible.)
// ---------------------------------------------------------------------------
__global__ void k_detect(const int* x32) {
    if (threadIdx.x == 0) {
        int f = 1;
        for (int i = 1; i < 64; i += 2)
            if (x32[i] != 0) f = 0;
        g_xflag = f;
    }
}

// Zero h[0] and c. 512 blocks x 256 threads, one float4 each.
__global__ void k_init() {
    int id = blockIdx.x * blockDim.x + threadIdx.x;   // 0..131071
    float4 z = make_float4(0.f, 0.f, 0.f, 0.f);
    if (id < (BATCH * HID / 4)) {
        ((float4*)g_h[0])[id] = z;
    } else {
        ((float4*)g_c)[id - (BATCH * HID / 4)] = z;
    }
}

// xtable[v][4u+g] = b_g[u] + sum_e embed[v][e] * W_gx[u][e]  (gate-interleaved)
__global__ void k_prep(const float* __restrict__ embed,
                       const float* __restrict__ Wg, const float* __restrict__ Wi,
                       const float* __restrict__ Wf, const float* __restrict__ Wo,
                       const float* __restrict__ bg, const float* __restrict__ bi,
                       const float* __restrict__ bfp, const float* __restrict__ bo) {
    int id = blockIdx.x * 256 + threadIdx.x;          // 0..40959
    int v   = id >> 12;                               // vocab index
    int col = id & (G4H - 1);
    int u   = col >> 2;
    int gi  = col & 3;
    const float* W  = (gi == 0) ? Wg : (gi == 1) ? Wi : (gi == 2) ? Wf : Wo;
    const float* bb = (gi == 0) ? bg : (gi == 1) ? bi : (gi == 2) ? bfp : bo;
    float s = bb[u];
#pragma unroll
    for (int e = 0; e < EMB; e++)
        s += embed[v * EMB + e] * W[u * EMB + e];
    g_xt[id] = s;
}

// Interleave recurrent weights: g_Wr[4u+gate][k] = W_gate_h[u][k]
__global__ void k_reorder(const float* __restrict__ Wg, const float* __restrict__ Wi,
                          const float* __restrict__ Wf, const float* __restrict__ Wo) {
    int r  = blockIdx.x;                              // 0..4095
    int u  = r >> 2;
    int gi = r & 3;
    const float* W = (gi == 0) ? Wg : (gi == 1) ? Wi : (gi == 2) ? Wf : Wo;
    float4 v = ((const float4*)(W + u * HID))[threadIdx.x];
    ((float4*)(g_Wr + r * HID))[threadIdx.x] = v;
}

// ---------------------------------------------------------------------------
// One timestep: z = h_in @ Wr^T (+ xtable[token]), gates, c/h update.
// Grid: (64, 2)  -> N-slice of 64 z-cols (16 hidden units) x M-tile of 128 rows.
// Block: 256 threads, thread (tx,ty): tx in 0..15 owns one hidden unit
// (4 consecutive z columns), ty in 0..15 owns 8 batch rows (ty + 16*i).
// ---------------------------------------------------------------------------
#define SA 36                                         // As row stride (pad)
#define BADDR(k, n) ((k) * 68 + (n) + (((n) & 32) >> 4))

__global__ void __launch_bounds__(256, 1) k_step(const void* __restrict__ xin, int t) {
    __shared__ float As[128 * SA];                    // 18 KB
    __shared__ float Bs[32 * 68 + 8];                 // ~8.7 KB, column-gap swizzle

    const float* __restrict__ hin  = g_h[t & 1];
    float* __restrict__       hout = g_h[(t + 1) & 1];

    int tid = threadIdx.x;
    int tx = tid & 15, ty = tid >> 4;
    int m0   = blockIdx.y * 128;
    int u0   = blockIdx.x * 16;
    int col0 = u0 * 4;

    u64 acc[8][2];
#pragma unroll
    for (int i = 0; i < 8; i++) { acc[i][0] = 0ULL; acc[i][1] = 0ULL; }

    for (int kc = 0; kc < HID; kc += 32) {
        __syncthreads();
        // Fill A tile: 128 rows x 32 k  (coalesced float4 loads of h)
#pragma unroll
        for (int q = 0; q < 4; q++) {
            int lin = tid + q * 256;                  // 0..1023 float4s
            int row = lin >> 3, kq = lin & 7;
            float4 v = *(const float4*)&hin[(m0 + row) * HID + kc + kq * 4];
            *(float4*)&As[row * SA + kq * 4] = v;
        }
        // Fill B tile: 64 n x 32 k, stored k-major with bank-gap swizzle
#pragma unroll
        for (int q = 0; q < 2; q++) {
            int lin = tid + q * 256;                  // 0..511 float4s
            int n = lin >> 3, kq = lin & 7;
            float4 v = *(const float4*)&g_Wr[(col0 + n) * HID + kc + kq * 4];
            int k4 = kq * 4;
            Bs[BADDR(k4 + 0, n)] = v.x;
            Bs[BADDR(k4 + 1, n)] = v.y;
            Bs[BADDR(k4 + 2, n)] = v.z;
            Bs[BADDR(k4 + 3, n)] = v.w;
        }
        __syncthreads();

#pragma unroll
        for (int kk = 0; kk < 32; kk += 2) {
            u64 b00 = *(const u64*)&Bs[BADDR(kk,     tx * 4)];
            u64 b01 = *(const u64*)&Bs[BADDR(kk,     tx * 4 + 2)];
            u64 b10 = *(const u64*)&Bs[BADDR(kk + 1, tx * 4)];
            u64 b11 = *(const u64*)&Bs[BADDR(kk + 1, tx * 4 + 2)];
#pragma unroll
            for (int i = 0; i < 8; i++) {
                float2 av = *(const float2*)&As[(ty + 16 * i) * SA + kk];
                u64 a0 = pk2(av.x, av.x);
                u64 a1 = pk2(av.y, av.y);
                acc[i][0] = ffma2(a0, b00, acc[i][0]);
                acc[i][1] = ffma2(a0, b01, acc[i][1]);
                acc[i][0] = ffma2(a1, b10, acc[i][0]);
                acc[i][1] = ffma2(a1, b11, acc[i][1]);
            }
        }
    }

    // Fused epilogue: add token projection, gates, update c and h.
    const long long* x64 = (const long long*)xin;
    const int*       x32 = (const int*)xin;
    int xf = g_xflag;
    int u = u0 + tx;
#pragma unroll
    for (int i = 0; i < 8; i++) {
        int m = m0 + ty + 16 * i;
        int v = xf ? (int)x64[m * SEQT + t] : x32[m * SEQT + t];
        float4 xt = *(const float4*)&g_xt[v * G4H + 4 * u];
        float z0, z1, z2, z3;
        upk2(acc[i][0], z0, z1);
        upk2(acc[i][1], z2, z3);
        float gg = tanhf(z0 + xt.x);
        float ii = 1.f / (1.f + expf(-(z1 + xt.y)));
        float ff = 1.f / (1.f + expf(-(z2 + xt.z)));
        float oo = 1.f / (1.f + expf(-(z3 + xt.w)));
        int idx = m * HID + u;
        float c = gg * ii + g_c[idx] * ff;
        g_c[idx] = c;
        hout[idx] = tanhf(c) * oo;
    }
}

// Final projection: y = h_T @ W_ph^T + b_p   (256 x 10)
__global__ void k_out(const float* __restrict__ Wp, const float* __restrict__ bp,
                      float* __restrict__ out) {
    __shared__ float s[NCLS * 128];
    int b = blockIdx.x, tid = threadIdx.x;            // 128 threads
    const float* h = g_h[0] + b * HID;                // last write was t=255 -> buf 0
    float acc[NCLS];
#pragma unroll
    for (int c = 0; c < NCLS; c++) acc[c] = 0.f;
    for (int k = tid; k < HID; k += 128) {
        float hv = h[k];
#pragma unroll
        for (int c = 0; c < NCLS; c++) acc[c] += hv * Wp[c * HID + k];
    }
#pragma unroll
    for (int c = 0; c < NCLS; c++) s[c * 128 + tid] = acc[c];
    __syncthreads();
    if (tid < NCLS) {
        float sum = bp[tid];
        for (int j = 0; j < 128; j++) sum += s[tid * 128 + j];
        out[b * NCLS + tid] = sum;
    }
}

// ---------------------------------------------------------------------------
// Inputs (metadata order): x, embed, W_gx, W_ix, W_fx, W_ox,
//   W_gh, W_ih, W_fh, W_oh, W_ph, b_g, b_i, b_f, b_o, b_p
// ---------------------------------------------------------------------------
extern "C" void kernel_launch(void* const* d_in, const int* in_sizes, int n_in,
                              void* d_out, int out_size) {
    (void)in_sizes; (void)n_in; (void)out_size;
    const void*  x     = d_in[0];
    const float* embed = (const float*)d_in[1];
    const float* Wgx   = (const float*)d_in[2];
    const float* Wix   = (const float*)d_in[3];
    const float* Wfx   = (const float*)d_in[4];
    const float* Wox   = (const float*)d_in[5];
    const float* Wgh   = (const float*)d_in[6];
    const float* Wih   = (const float*)d_in[7];
    const float* Wfh   = (const float*)d_in[8];
    const float* Woh   = (const float*)d_in[9];
    const float* Wph   = (const float*)d_in[10];
    const float* bg    = (const float*)d_in[11];
    const float* bi    = (const float*)d_in[12];
    const float* bfp   = (const float*)d_in[13];
    const float* bo    = (const float*)d_in[14];
    const float* bp    = (const float*)d_in[15];

    k_detect<<<1, 32>>>((const int*)x);
    k_init<<<512, 256>>>();
    k_prep<<<160, 256>>>(embed, Wgx, Wix, Wfx, Wox, bg, bi, bfp, bo);
    k_reorder<<<4096, 256>>>(Wgh, Wih, Wfh, Woh);

    for (int t = 0; t < SEQT; t++)
        k_step<<<dim3(64, 2), 256>>>(x, t);

    k_out<<<256, 128>>>(Wph, bp, (float*)d_out);
}

// round 13
// speedup vs baseline: 2.8792x; 2.8792x over previous
#include <cuda_runtime.h>
#include <cuda_bf16.h>
#include <cstdint>

#define BATCH 256
#define SEQT  256
#define HID   1024
#define G4H   4096
#define EMB   10
#define NVOC  10
#define NCLS  10

#define STG        49152                 // stage: Ahi 8K | Alo 8K | Bhi 16K | Blo 16K
#define SMEM_TOTAL (3 * STG)

// Device-global scratch (allocation-free rule)
__device__ __nv_bfloat16 g_Whi[G4H * HID];        // 8 MB  interleaved W hi
__device__ __nv_bfloat16 g_Wlo[G4H * HID];        // 8 MB  interleaved W lo
__device__ __nv_bfloat16 g_hA[2][BATCH * HID];    // h hi, double-buffered
__device__ __nv_bfloat16 g_hB[2][BATCH * HID];    // h lo
__device__ float g_c[BATCH * HID];
__device__ float g_xt[NVOC * G4H];
__device__ int   g_xflag;

// ------------------------- PTX helpers (all baseline sm_80+ features) ------
__device__ __forceinline__ uint32_t smem_u32(const void* p) {
    uint32_t a;
    asm("{ .reg .u64 t; cvta.to.shared.u64 t, %1; cvt.u32.u64 %0, t; }" : "=r"(a) : "l"(p));
    return a;
}
__device__ __forceinline__ void cp16(uint32_t dst, const void* src) {
    asm volatile("cp.async.cg.shared.global [%0], [%1], 16;" :: "r"(dst), "l"(src) : "memory");
}
#define CP_COMMIT() asm volatile("cp.async.commit_group;" ::: "memory")
#define CP_WAIT1()  asm volatile("cp.async.wait_group 1;" ::: "memory")
#define CP_WAIT0()  asm volatile("cp.async.wait_group 0;" ::: "memory")

__device__ __forceinline__ void ldsm4(uint32_t* r, uint32_t addr) {
    asm volatile("ldmatrix.sync.aligned.m8n8.x4.shared.b16 {%0,%1,%2,%3}, [%4];"
        : "=r"(r[0]), "=r"(r[1]), "=r"(r[2]), "=r"(r[3]) : "r"(addr));
}
__device__ __forceinline__ void hmma(float* d, const uint32_t* a, const uint32_t* b) {
    asm volatile("mma.sync.aligned.m16n8k16.row.col.f32.bf16.bf16.f32 "
        "{%0,%1,%2,%3}, {%4,%5,%6,%7}, {%8,%9}, {%0,%1,%2,%3};"
        : "+f"(d[0]), "+f"(d[1]), "+f"(d[2]), "+f"(d[3])
        : "r"(a[0]), "r"(a[1]), "r"(a[2]), "r"(a[3]), "r"(b[0]), "r"(b[1]));
}
__device__ __forceinline__ float tanh_f(float x) {
    float e = __expf(2.0f * x);
    return 1.0f - __fdividef(2.0f, e + 1.0f);
}
__device__ __forceinline__ float sig_f(float x) {
    return __fdividef(1.0f, 1.0f + __expf(-x));
}

// ------------------------- setup kernels -------------------------
__global__ void k_detect(const int* x32) {
    if (threadIdx.x == 0) {
        int f = 1;
        for (int i = 1; i < 64; i += 2)
            if (x32[i] != 0) f = 0;
        g_xflag = f;
    }
}
__global__ void k_zero() {
    int id = blockIdx.x * 256 + threadIdx.x;          // 0..131071
    uint4 z = make_uint4(0, 0, 0, 0);
    if (id < 32768)      ((uint4*)g_hA[0])[id] = z;
    else if (id < 65536) ((uint4*)g_hB[0])[id - 32768] = z;
    else                 ((uint4*)g_c)[id - 65536] = z;
}
__global__ void k_prep(const float* __restrict__ embed,
                       const float* __restrict__ Wg, const float* __restrict__ Wi,
                       const float* __restrict__ Wf, const float* __restrict__ Wo,
                       const float* __restrict__ bg, const float* __restrict__ bi,
                       const float* __restrict__ bfp, const float* __restrict__ bo) {
    int id = blockIdx.x * 256 + threadIdx.x;          // 0..40959
    int v = id >> 12, col = id & (G4H - 1);
    int u = col >> 2, gi = col & 3;
    const float* W  = (gi == 0) ? Wg : (gi == 1) ? Wi : (gi == 2) ? Wf : Wo;
    const float* bb = (gi == 0) ? bg : (gi == 1) ? bi : (gi == 2) ? bfp : bo;
    float s = bb[u];
#pragma unroll
    for (int e = 0; e < EMB; e++)
        s += embed[v * EMB + e] * W[u * EMB + e];
    g_xt[id] = s;
}
// gate-interleave + bf16 hi/lo split of recurrent weights: row 4u+gate
__global__ void k_split(const float* __restrict__ Wg, const float* __restrict__ Wi,
                        const float* __restrict__ Wf, const float* __restrict__ Wo) {
    int r = blockIdx.x, u = r >> 2, gi = r & 3;
    const float* W = (gi == 0) ? Wg : (gi == 1) ? Wi : (gi == 2) ? Wf : Wo;
    int c0 = threadIdx.x * 4;
    float4 w = *(const float4*)&W[u * HID + c0];
    float ws[4] = {w.x, w.y, w.z, w.w};
    __align__(8) __nv_bfloat16 hi[4], lo[4];
#pragma unroll
    for (int j = 0; j < 4; j++) {
        hi[j] = __float2bfloat16(ws[j]);
        lo[j] = __float2bfloat16(ws[j] - __bfloat162float(hi[j]));
    }
    *(uint2*)&g_Whi[r * HID + c0] = *(uint2*)hi;
    *(uint2*)&g_Wlo[r * HID + c0] = *(uint2*)lo;
}

// ------------------------- the timestep kernel -------------------------
// grid (32, 4): bx = N-tile (128 gate cols), by = M-tile (64 batch rows)
// 128 threads = 4 warps in a 2x2 warp grid; warp tile 32(M) x 64(N).
// z = hA@Whi^T + hA@Wlo^T + hB@Whi^T  (fp32 HMMA accum)
__global__ void __launch_bounds__(128, 1) k_step(const void* __restrict__ xin, int t) {
    extern __shared__ __align__(1024) char smem[];
    uint32_t sb = smem_u32(smem);
    int tid = threadIdx.x, wid = tid >> 5, lane = tid & 31;
    int n0 = blockIdx.x * 128, m0 = blockIdx.y * 64;

    const __nv_bfloat16* __restrict__ hA = g_hA[t & 1];
    const __nv_bfloat16* __restrict__ hB = g_hB[t & 1];
    __nv_bfloat16* __restrict__ hoA = g_hA[(t + 1) & 1];
    __nv_bfloat16* __restrict__ hoB = g_hB[(t + 1) & 1];

    // ---- load one K-chunk (64 k) into a stage (SW swizzle on 16B units) ----
    auto load_chunk = [&](int c, int s) {
        uint32_t s0 = sb + s * STG;
        int kc = c * 64;
#pragma unroll
        for (int it = 0; it < 4; it++) {
            int idx = tid + it * 128;                 // 0..511: A rows 64 x 8 chunks
            int row = idx >> 3, c16 = idx & 7;
            uint32_t off = row * 128 + ((c16 ^ (row & 7)) * 16);
            int src = (m0 + row) * HID + kc + c16 * 8;
            cp16(s0 + off,        hA + src);
            cp16(s0 + 8192 + off, hB + src);
        }
#pragma unroll
        for (int it = 0; it < 8; it++) {
            int idx = tid + it * 128;                 // 0..1023: B rows 128 x 8 chunks
            int row = idx >> 3, c16 = idx & 7;
            uint32_t off = row * 128 + ((c16 ^ (row & 7)) * 16);
            int src = (n0 + row) * HID + kc + c16 * 8;
            cp16(s0 + 16384 + off, g_Whi + src);
            cp16(s0 + 32768 + off, g_Wlo + src);
        }
    };

    int wr = wid >> 1, wc = wid & 1;                  // warp coords in 2x2
    int ar0 = 32 * wr;                                // warp A-row base (of 64)
    int bn0 = 64 * wc;                                // warp B-row base (of 128)
    float acc[2][8][4];
#pragma unroll
    for (int mt = 0; mt < 2; mt++)
#pragma unroll
        for (int nb = 0; nb < 8; nb++)
#pragma unroll
            for (int q = 0; q < 4; q++) acc[mt][nb][q] = 0.f;

    auto compute_chunk = [&](uint32_t s0) {
        uint32_t Ab[2] = {s0, s0 + 8192};
        uint32_t Bb[2] = {s0 + 16384, s0 + 32768};
#pragma unroll
        for (int term = 0; term < 3; term++) {
            uint32_t Abase = Ab[term >> 1];           // terms 0,1: Ahi; term 2: Alo
            uint32_t Bbase = Bb[term == 1 ? 1 : 0];   // term 1: Blo; else Bhi
#pragma unroll
            for (int kk = 0; kk < 64; kk += 16) {
                uint32_t a[2][4];
#pragma unroll
                for (int mt = 0; mt < 2; mt++) {
                    int r = ar0 + mt * 16 + (lane & 15);
                    int kch = (kk >> 3) + (lane >> 4);
                    ldsm4(a[mt], Abase + r * 128 + ((kch ^ (r & 7)) * 16));
                }
#pragma unroll
                for (int nb2 = 0; nb2 < 4; nb2++) {
                    uint32_t b[4];
                    int nr = bn0 + nb2 * 16 + ((lane >> 4) * 8) + (lane & 7);
                    int kch = (kk >> 3) + ((lane >> 3) & 1);
                    ldsm4(b, Bbase + nr * 128 + ((kch ^ (nr & 7)) * 16));
                    hmma(acc[0][2 * nb2],     a[0], b);
                    hmma(acc[0][2 * nb2 + 1], a[0], b + 2);
                    hmma(acc[1][2 * nb2],     a[1], b);
                    hmma(acc[1][2 * nb2 + 1], a[1], b + 2);
                }
            }
        }
    };

    load_chunk(0, 0); CP_COMMIT();
    load_chunk(1, 1); CP_COMMIT();
    for (int c = 0; c < 16; c++) {
        if (c >= 14) CP_WAIT0(); else CP_WAIT1();
        __syncthreads();
        if (c < 14) { load_chunk(c + 2, (c + 2) % 3); CP_COMMIT(); }
        compute_chunk(sb + (c % 3) * STG);
    }
    __syncthreads();

    // ---- park z in SMEM (stride 132 floats), then fused LSTM epilogue ----
    float* zs = (float*)smem;
#pragma unroll
    for (int mt = 0; mt < 2; mt++)
#pragma unroll
        for (int nb = 0; nb < 8; nb++) {
            int r = 32 * wr + mt * 16 + (lane >> 2);
            int cc = 64 * wc + nb * 8 + 2 * (lane & 3);
            *(float2*)&zs[r * 132 + cc]       = make_float2(acc[mt][nb][0], acc[mt][nb][1]);
            *(float2*)&zs[(r + 8) * 132 + cc] = make_float2(acc[mt][nb][2], acc[mt][nb][3]);
        }
    __syncthreads();

    int row = tid >> 1, half = tid & 1;
    int m = m0 + row;
    int v = g_xflag ? (int)((const long long*)xin)[m * SEQT + t]
                    : ((const int*)xin)[m * SEQT + t];
    int gcb = n0 + 64 * half;                         // global gate-col base
    int ub = gcb >> 2;                                // 16 hidden units per thread
    const float* zr = &zs[row * 132 + 64 * half];
    float cn[16];
    __align__(16) __nv_bfloat16 h16[16], l16[16];
#pragma unroll
    for (int q = 0; q < 4; q++) {
        float4 cold = *(const float4*)&g_c[m * HID + ub + 4 * q];
        float co[4] = {cold.x, cold.y, cold.z, cold.w};
#pragma unroll
        for (int jj = 0; jj < 4; jj++) {
            int j = 4 * q + jj;
            float4 z4 = *(const float4*)&zr[4 * j];
            float4 xt = *(const float4*)&g_xt[v * G4H + gcb + 4 * j];
            float gg = tanh_f(z4.x + xt.x);
            float ii = sig_f(z4.y + xt.y);
            float ff = sig_f(z4.z + xt.z);
            float oo = sig_f(z4.w + xt.w);
            float cc = gg * ii + co[jj] * ff;
            cn[j] = cc;
            float hv = tanh_f(cc) * oo;
            h16[j] = __float2bfloat16(hv);
            l16[j] = __float2bfloat16(hv - __bfloat162float(h16[j]));
        }
    }
#pragma unroll
    for (int q = 0; q < 4; q++)
        *(float4*)&g_c[m * HID + ub + 4 * q] =
            make_float4(cn[4 * q], cn[4 * q + 1], cn[4 * q + 2], cn[4 * q + 3]);
    *(uint4*)&hoA[m * HID + ub]     = ((uint4*)h16)[0];
    *(uint4*)&hoA[m * HID + ub + 8] = ((uint4*)h16)[1];
    *(uint4*)&hoB[m * HID + ub]     = ((uint4*)l16)[0];
    *(uint4*)&hoB[m * HID + ub + 8] = ((uint4*)l16)[1];
}

// ------------------------- final projection -------------------------
__global__ void k_out(const float* __restrict__ Wp, const float* __restrict__ bp,
                      float* __restrict__ out) {
    __shared__ float s[NCLS * 128];
    int b = blockIdx.x, tid = threadIdx.x;
    const __nv_bfloat16* hA = g_hA[0] + b * HID;      // after t=255, h lives in buf 0
    const __nv_bfloat16* hB = g_hB[0] + b * HID;
    float acc[NCLS];
#pragma unroll
    for (int c = 0; c < NCLS; c++) acc[c] = 0.f;
    for (int k = tid; k < HID; k += 128) {
        float hv = __bfloat162float(hA[k]) + __bfloat162float(hB[k]);
#pragma unroll
        for (int c = 0; c < NCLS; c++) acc[c] += hv * Wp[c * HID + k];
    }
#pragma unroll
    for (int c = 0; c < NCLS; c++) s[c * 128 + tid] = acc[c];
    __syncthreads();
    if (tid < NCLS) {
        float sum = bp[tid];
        for (int j = 0; j < 128; j++) sum += s[tid * 128 + j];
        out[b * NCLS + tid] = sum;
    }
}

// ------------------------- launch -------------------------
extern "C" void kernel_launch(void* const* d_in, const int* in_sizes, int n_in,
                              void* d_out, int out_size) {
    (void)in_sizes; (void)n_in; (void)out_size;
    const void*  x     = d_in[0];
    const float* embed = (const float*)d_in[1];
    const float* Wgx = (const float*)d_in[2],  *Wix = (const float*)d_in[3];
    const float* Wfx = (const float*)d_in[4],  *Wox = (const float*)d_in[5];
    const float* Wgh = (const float*)d_in[6],  *Wih = (const float*)d_in[7];
    const float* Wfh = (const float*)d_in[8],  *Woh = (const float*)d_in[9];
    const float* Wph = (const float*)d_in[10];
    const float* bg = (const float*)d_in[11],  *bi = (const float*)d_in[12];
    const float* bfp = (const float*)d_in[13], *bo = (const float*)d_in[14];
    const float* bp = (const float*)d_in[15];

    cudaFuncSetAttribute(k_step, cudaFuncAttributeMaxDynamicSharedMemorySize, SMEM_TOTAL);

    k_detect<<<1, 32>>>((const int*)x);
    k_zero<<<512, 256>>>();
    k_prep<<<160, 256>>>(embed, Wgx, Wix, Wfx, Wox, bg, bi, bfp, bo);
    k_split<<<4096, 256>>>(Wgh, Wih, Wfh, Woh);

    for (int t = 0; t < SEQT; t++)
        k_step<<<dim3(32, 4), 128, SMEM_TOTAL>>>(x, t);

    k_out<<<256, 128>>>(Wph, bp, (float*)d_out);
}